// round 10
// baseline (speedup 1.0000x reference)
#include <cuda_runtime.h>

// UnPatcher: 2-level inverse Haar DWT, fully fused.
// in : [8, 256, 96, 96]  f32   (channels = 16 out-ch x 4 (level2 m) x 4 (level1 n))
// out: [8, 16, 384, 384] f32
//
// out[b,c, 4i + 2*p1 + p, 4j + 2*q1 + q] =
//   sum_{m,n} in[b, c + 16m + 64n, i, j] * (-1)^{(m&1)p + (m>>1)q + (n&1)p1 + (n>>1)q1}
// (rescaled Haar gain is exactly 1 per level -> all coefficients are +/-1)
//
// Exact R3 geometry (best, 27.1us): one thread per input site, 16 scalar
// coalesced loads (1 line/warp), 4 float4 stores (4 lines/warp). Single
// change: OUTPUT stores carry an L2 evict_last cache-hint policy. Rationale:
// there is zero intra-replay reuse; across graph replays the output is
// re-dirtied in place, so if its 75.5 MB (< 126 MB L2) stays resident,
// dirty lines are overwritten without ever writing back to DRAM -> per-replay
// DRAM traffic drops from ~103 MB to ~input reads only. (R8 proved the
// cache_hint path itself is perf-neutral; R6's regression was __stcs which
// is the opposite priority AND degrades the L1 path.)

#define BATCH  8
#define CO     16
#define HI     96
#define WI     96
#define CHS    (CO * HI * WI)          // element stride between the 16 channel groups
#define TOTAL  (BATCH * CO * HI * WI)  // one thread per input spatial site = 1179648

__device__ __forceinline__ unsigned long long make_evict_last_policy()
{
    unsigned long long pol;
    asm("createpolicy.fractional.L2::evict_last.b64 %0, 1.0;" : "=l"(pol));
    return pol;
}

__device__ __forceinline__ void stg_v4_hint(float4* p, float4 o, unsigned long long pol)
{
    asm volatile("st.global.L2::cache_hint.v4.f32 [%0], {%1,%2,%3,%4}, %5;"
                 :: "l"(p), "f"(o.x), "f"(o.y), "f"(o.z), "f"(o.w), "l"(pol)
                 : "memory");
}

__global__ void __launch_bounds__(256)
unpatcher_fused_ohint_kernel(const float* __restrict__ in, float* __restrict__ out)
{
    int t = blockIdx.x * 256 + threadIdx.x;   // grid covers TOTAL exactly

    int j   = t % WI;
    int tmp = t / WI;
    int i   = tmp % HI;
    int bc  = tmp / HI;        // b*16 + c
    int b   = bc >> 4;
    int c   = bc & 15;

    // 16 coalesced default-policy loads: v[4n + m] = in[b, c + 16m + 64n, i, j]
    const float* __restrict__ base =
        in + (((size_t)(b * 256 + c)) * HI + i) * WI + j;

    float v[16];
#pragma unroll
    for (int k = 0; k < 16; k++)
        v[k] = __ldg(base + (size_t)k * CHS);

    // Stage 1: height butterfly -> h[width-combo][patch row r = 2*p1 + p]
    float h[4][4];
#pragma unroll
    for (int nw = 0; nw < 2; nw++) {
#pragma unroll
        for (int mw = 0; mw < 2; mw++) {
            float c00 = v[8 * nw + 2 * mw + 0];  // nh=0, mh=0
            float c01 = v[8 * nw + 2 * mw + 1];  // nh=0, mh=1
            float c10 = v[8 * nw + 2 * mw + 4];  // nh=1, mh=0
            float c11 = v[8 * nw + 2 * mw + 5];  // nh=1, mh=1
            float u0 = c00 + c01, u1 = c00 - c01;   // level-2 height bit
            float w0 = c10 + c11, w1 = c10 - c11;
            int wi_ = 2 * nw + mw;
            h[wi_][0] = u0 + w0;   // p=0, p1=0
            h[wi_][1] = u1 + w1;   // p=1, p1=0
            h[wi_][2] = u0 - w0;   // p=0, p1=1
            h[wi_][3] = u1 - w1;   // p=1, p1=1
        }
    }

    const unsigned long long pol = make_evict_last_policy();

    // Stage 2: width butterfly + one evict_last float4 store per patch row.
    // Adjacent lanes (consecutive j) write adjacent float4s -> fully coalesced.
    float4* obase = (float4*)(out + ((size_t)bc * (4 * HI) + 4 * i) * (4 * WI)) + j;

#pragma unroll
    for (int r = 0; r < 4; r++) {
        float d00 = h[0][r], d01 = h[1][r], d10 = h[2][r], d11 = h[3][r];
        float a0 = d00 + d01, a1 = d00 - d01;   // level-2 width bit
        float b0 = d10 + d11, b1 = d10 - d11;
        float4 o;
        o.x = a0 + b0;   // q=0, q1=0
        o.y = a1 + b1;   // q=1, q1=0
        o.z = a0 - b0;   // q=0, q1=1
        o.w = a1 - b1;   // q=1, q1=1
        stg_v4_hint(obase + r * WI, o, pol);   // output row = 384 f32 = 96 float4s
    }
}

extern "C" void kernel_launch(void* const* d_in, const int* in_sizes, int n_in,
                              void* d_out, int out_size)
{
    const float* x = (const float*)d_in[0];
    float* y       = (float*)d_out;
    (void)in_sizes; (void)n_in; (void)out_size;

    unpatcher_fused_ohint_kernel<<<TOTAL / 256, 256>>>(x, y);   // 4608 blocks
}

// round 11
// speedup vs baseline: 1.0444x; 1.0444x over previous
#include <cuda_runtime.h>

// UnPatcher: 2-level inverse Haar DWT, fully fused.
// in : [8, 256, 96, 96]  f32   (channels = 16 out-ch x 4 (level2 m) x 4 (level1 n))
// out: [8, 16, 384, 384] f32
//
// out[b,c, 4i + 2*p1 + p, 4j + 2*q1 + q] =
//   sum_{m,n} in[b, c + 16m + 64n, i, j] * (-1)^{(m&1)p + (m>>1)q + (n&1)p1 + (n>>1)q1}
// (rescaled Haar gain is exactly 1 per level -> all coefficients are +/-1)
//
// Exact R3 memory geometry (16 scalar 1-line/warp loads, 4 default float4
// stores). Change vs R3: the 16 loads are split into two batches of 8 with
// the nw=0 stage-1 butterfly computed between them, and a fake register
// dependency pinning batch 2 below that compute. This halves MLP_p1
// (front-batched consecutive LDGs) from 16 to 8 to cut cross-CTA L1tex
// wavefront-queue contention (B300 spr_max model), at no loss of per-SM
// aggregate MLP (52 warps cover the exposure).

#define BATCH  8
#define CO     16
#define HI     96
#define WI     96
#define CHS    (CO * HI * WI)          // element stride between the 16 channel groups
#define TOTAL  (BATCH * CO * HI * WI)  // one thread per input spatial site = 1179648

__global__ void __launch_bounds__(256)
unpatcher_fused_split_kernel(const float* __restrict__ in, float* __restrict__ out)
{
    int t = blockIdx.x * 256 + threadIdx.x;   // grid covers TOTAL exactly

    int j   = t % WI;
    int tmp = t / WI;
    int i   = tmp % HI;
    int bc  = tmp / HI;        // b*16 + c
    int b   = bc >> 4;
    int c   = bc & 15;

    const float* __restrict__ base =
        in + (((size_t)(b * 256 + c)) * HI + i) * WI + j;

    // ---- Batch 1: nw=0 channel block, v[0..7] (8 consecutive LDGs) ----
    float v0[8];
#pragma unroll
    for (int k = 0; k < 8; k++)
        v0[k] = __ldg(base + (size_t)k * CHS);

    // Stage 1 butterfly for nw=0  ->  h[0][*], h[1][*]
    float h[4][4];
#pragma unroll
    for (int mw = 0; mw < 2; mw++) {
        float c00 = v0[2 * mw + 0];  // nh=0, mh=0
        float c01 = v0[2 * mw + 1];  // nh=0, mh=1
        float c10 = v0[2 * mw + 4];  // nh=1, mh=0
        float c11 = v0[2 * mw + 5];  // nh=1, mh=1
        float u0 = c00 + c01, u1 = c00 - c01;   // level-2 height bit
        float w0 = c10 + c11, w1 = c10 - c11;
        h[mw][0] = u0 + w0;   // p=0, p1=0
        h[mw][1] = u1 + w1;   // p=1, p1=0
        h[mw][2] = u0 - w0;   // p=0, p1=1
        h[mw][3] = u1 - w1;   // p=1, p1=1
    }

    // Fake dependency: batch-2 base depends on batch-1 results, so ptxas
    // cannot hoist the second 8 LDGs above the compute (keeps MLP_p1 = 8).
    const float* base_hi = base + (size_t)8 * CHS;
    asm volatile("" : "+l"(base_hi) : "f"(h[0][0]), "f"(h[1][3]));

    // ---- Batch 2: nw=1 channel block, v[8..15] ----
    float v1[8];
#pragma unroll
    for (int k = 0; k < 8; k++)
        v1[k] = __ldg(base_hi + (size_t)k * CHS);

    // Stage 1 butterfly for nw=1  ->  h[2][*], h[3][*]
#pragma unroll
    for (int mw = 0; mw < 2; mw++) {
        float c00 = v1[2 * mw + 0];
        float c01 = v1[2 * mw + 1];
        float c10 = v1[2 * mw + 4];
        float c11 = v1[2 * mw + 5];
        float u0 = c00 + c01, u1 = c00 - c01;
        float w0 = c10 + c11, w1 = c10 - c11;
        h[2 + mw][0] = u0 + w0;
        h[2 + mw][1] = u1 + w1;
        h[2 + mw][2] = u0 - w0;
        h[2 + mw][3] = u1 - w1;
    }

    // Stage 2: width butterfly + one default float4 store per patch row.
    // Adjacent lanes (consecutive j) write adjacent float4s -> fully coalesced.
    float4* obase = (float4*)(out + ((size_t)bc * (4 * HI) + 4 * i) * (4 * WI)) + j;

#pragma unroll
    for (int r = 0; r < 4; r++) {
        float d00 = h[0][r], d01 = h[1][r], d10 = h[2][r], d11 = h[3][r];
        float a0 = d00 + d01, a1 = d00 - d01;   // level-2 width bit
        float b0 = d10 + d11, b1 = d10 - d11;
        float4 o;
        o.x = a0 + b0;   // q=0, q1=0
        o.y = a1 + b1;   // q=1, q1=0
        o.z = a0 - b0;   // q=0, q1=1
        o.w = a1 - b1;   // q=1, q1=1
        obase[r * WI] = o;   // output row = 384 f32 = 96 float4s
    }
}

extern "C" void kernel_launch(void* const* d_in, const int* in_sizes, int n_in,
                              void* d_out, int out_size)
{
    const float* x = (const float*)d_in[0];
    float* y       = (float*)d_out;
    (void)in_sizes; (void)n_in; (void)out_size;

    unpatcher_fused_split_kernel<<<TOTAL / 256, 256>>>(x, y);   // 4608 blocks
}